// round 16
// baseline (speedup 1.0000x reference)
#include <cuda_runtime.h>

// LinearActorNet: B=2048, K=512, N=256, T=64. task_id/action int32.
// out layout (float32): [action(B) | log_prob(B) | entropy(B)]
//
// 3-stage deterministic pipeline:
//  1) setup:  64 CTAs x 256 thr, register-cached ballot compaction (once).
//  2) logits: grid (64 tasks x 4 slots x 4 K-quarters), 256 thr, TMR=16,
//     thread = (row-group, col pair): 8 rows x 2 cols x 128 k.
//     Explicit depth-2 register double-buffer on the W stream (A/B sets)
//     so 8 LDGs are always in flight under the FFMA2 block.
//  3) softmax: 1024 CTAs x 2 rows; sum 4 partials + bias, fused log-softmax.

#define BB 2048
#define KK 512
#define NN 256
#define TT 64
#define TMR 16
#define NSLOT 4
#define KSPLIT 4
#define KH 128
#define LSTRIDE 128

__device__ unsigned short g_list[TT * LSTRIDE];
__device__ int g_cnt[TT];
__device__ float g_part[KSPLIT][BB][NN];

union f2u { float2 f; unsigned long long u; };
__device__ __forceinline__ unsigned long long pk(float lo, float hi) {
    f2u u; u.f = make_float2(lo, hi); return u.u;
}
__device__ __forceinline__ float fold(unsigned long long v) {
    f2u u; u.u = v; return u.f.x + u.f.y;
}
#define FFMA2(d, a, b) \
    asm("fma.rn.f32x2 %0, %1, %2, %0;" : "+l"(d) : "l"(a), "l"(b))

// ---------------- setup: per-task parallel compaction ----------------
__global__ __launch_bounds__(256, 4)
void setup_kernel(const int* __restrict__ task_id)
{
    const int t    = blockIdx.x;
    const int lane = threadIdx.x & 31;
    const int w    = threadIdx.x >> 5;          // 0..7
    const unsigned lt = (1u << lane) - 1u;
    __shared__ int wcnt[8];

    int ids[8];
    #pragma unroll
    for (int i = 0; i < 8; i++)
        ids[i] = task_id[w * 256 + i * 32 + lane];

    int c = 0;
    #pragma unroll
    for (int i = 0; i < 8; i++)
        c += __popc(__ballot_sync(0xffffffffu, ids[i] == t));
    if (lane == 0) wcnt[w] = c;
    __syncthreads();
    int base = 0;
    #pragma unroll
    for (int i = 0; i < 8; i++) if (i < w) base += wcnt[i];
    if (w == 7 && lane == 0) g_cnt[t] = base + wcnt[7];

    #pragma unroll
    for (int i = 0; i < 8; i++) {
        bool p = (ids[i] == t);
        unsigned m = __ballot_sync(0xffffffffu, p);
        if (p) {
            int pos = base + __popc(m & lt);
            if (pos < LSTRIDE)
                g_list[t * LSTRIDE + pos] =
                    (unsigned short)(w * 256 + i * 32 + lane);
        }
        base += __popc(m);
    }
}

// ---------------- stage 1: split-K partial logits (pipelined W) ----------------
#define LOADW(d, p) do {                                              \
    const float* _wk = (p);                                           \
    d##0 = _wk[0];    d##1 = _wk[NN];     d##2 = _wk[2*NN];   d##3 = _wk[3*NN];   \
    d##4 = _wk[128];  d##5 = _wk[NN+128]; d##6 = _wk[2*NN+128]; d##7 = _wk[3*NN+128]; \
} while (0)

#define FMABLK(d, kk) do {                                            \
    unsigned long long wA0 = pk(d##0, d##1), wA1 = pk(d##2, d##3);    \
    unsigned long long wB0 = pk(d##4, d##5), wB1 = pk(d##6, d##7);    \
    _Pragma("unroll")                                                 \
    for (int m = 0; m < 8; m++) {                                     \
        ulonglong2 xv = *(const ulonglong2*)&xs_s[rg * 8 + m][kk];    \
        FFMA2(acc0[m], xv.x, wA0);                                    \
        FFMA2(acc0[m], xv.y, wA1);                                    \
        FFMA2(acc1[m], xv.x, wB0);                                    \
        FFMA2(acc1[m], xv.y, wB1);                                    \
    }                                                                 \
} while (0)

__global__ __launch_bounds__(256, 3)
void logits_kernel(const float* __restrict__ xs,
                   const float* __restrict__ W)
{
    __shared__ float xs_s[TMR][KH];              // 8 KB

    const int tid  = threadIdx.x;
    const int t    = blockIdx.x;
    const int slot = blockIdx.y;
    const int ks   = blockIdx.z;

    const int cnt = min(g_cnt[t], LSTRIDE);
    if (slot * TMR >= cnt) return;
    const unsigned short* __restrict__ lst = g_list + t * LSTRIDE;

    const int rg = tid >> 7;                     // rows rg*8 .. rg*8+7
    const int cl = tid & 127;                    // cols cl, cl+128
    const float* __restrict__ Wt =
        W + (size_t)t * (KK * NN) + (size_t)ks * KH * NN + cl;

    for (int tile = slot; tile * TMR < cnt; tile += NSLOT) {
        const int m0 = tile * TMR;
        const int mc = min(TMR, cnt - m0);
        __syncthreads();

        // ---- stage xs tile [TMR][KH] (float4, coalesced) ----
        #pragma unroll
        for (int i = 0; i < (TMR * KH / 4) / 256; i++) {   // 2 iters
            int idx = i * 256 + tid;
            int m = idx >> 5;                              // 32 float4 per row
            int cc = idx & 31;
            float4 v = make_float4(0.f, 0.f, 0.f, 0.f);
            if (m < mc) {
                const float4* src =
                    (const float4*)(xs + (size_t)lst[m0 + m] * KK + ks * KH);
                v = src[cc];
            }
            *(float4*)&xs_s[m][cc * 4] = v;
        }
        __syncthreads();

        // ---- GEMM, depth-2 register double-buffer on W ----
        unsigned long long acc0[8], acc1[8];
        #pragma unroll
        for (int m = 0; m < 8; m++) { acc0[m] = 0ull; acc1[m] = 0ull; }

        float A0, A1, A2, A3, A4, A5, A6, A7;
        float B0, B1, B2, B3, B4, B5, B6, B7;
        LOADW(A, Wt);
        #pragma unroll
        for (int k = 0; k < KH; k += 8) {
            LOADW(B, Wt + (size_t)(k + 4) * NN);           // prefetch
            FMABLK(A, k);
            if (k + 8 < KH) LOADW(A, Wt + (size_t)(k + 8) * NN);
            FMABLK(B, k + 4);
        }

        // ---- store partials (coalesced) ----
        #pragma unroll
        for (int m = 0; m < 8; m++) {
            int r = rg * 8 + m;
            if (r < mc) {
                float* dst = &g_part[ks][lst[m0 + r]][0];
                dst[cl]       = fold(acc0[m]);
                dst[cl + 128] = fold(acc1[m]);
            }
        }
    }
}

// ---------------- stage 2: bias + fused log-softmax + outputs ----------------
#define RW 2
__global__ __launch_bounds__(256, 6)
void softmax_kernel(const int* __restrict__ task_id,
                    const int* __restrict__ action,
                    const float* __restrict__ bias,
                    float* __restrict__ out)
{
    __shared__ float redm[RW][8];
    __shared__ float reda[RW][8];
    __shared__ float redb[RW][8];

    const int tid  = threadIdx.x;           // column n = tid
    const int row0 = blockIdx.x * RW;
    const int lane = tid & 31;
    const int wid  = tid >> 5;

    float v[RW];
    #pragma unroll
    for (int r = 0; r < RW; r++) {
        const int row = row0 + r;
        const int t   = task_id[row];
        v[r] = (g_part[0][row][tid] + g_part[1][row][tid])
             + (g_part[2][row][tid] + g_part[3][row][tid])
             + bias[t * NN + tid];
    }

    float mx[RW];
    #pragma unroll
    for (int r = 0; r < RW; r++) {
        float x = v[r];
        #pragma unroll
        for (int o = 16; o > 0; o >>= 1)
            x = fmaxf(x, __shfl_xor_sync(0xffffffffu, x, o));
        if (lane == 0) redm[r][wid] = x;
    }
    __syncthreads();
    #pragma unroll
    for (int r = 0; r < RW; r++) {
        float x = redm[r][0];
        #pragma unroll
        for (int w = 1; w < 8; w++) x = fmaxf(x, redm[r][w]);
        mx[r] = x;
    }

    #pragma unroll
    for (int r = 0; r < RW; r++) {
        float d = v[r] - mx[r];
        float e = __expf(d);
        float s1 = e, s2 = e * d;
        #pragma unroll
        for (int o = 16; o > 0; o >>= 1) {
            s1 += __shfl_xor_sync(0xffffffffu, s1, o);
            s2 += __shfl_xor_sync(0xffffffffu, s2, o);
        }
        if (lane == 0) { reda[r][wid] = s1; redb[r][wid] = s2; }
    }
    __syncthreads();

    #pragma unroll
    for (int r = 0; r < RW; r++) {
        float s1 = 0.f, s2 = 0.f;
        #pragma unroll
        for (int w = 0; w < 8; w++) { s1 += reda[r][w]; s2 += redb[r][w]; }
        const int   row  = row0 + r;
        const int   a    = action[row];
        const float logS = logf(s1);
        if (tid == a)
            out[BB + row] = v[r] - mx[r] - logS;       // log_prob
        if (tid == 0) {
            out[row]          = (float)a;              // action (as float)
            out[2 * BB + row] = logS - s2 / s1;        // entropy
        }
    }
}

extern "C" void kernel_launch(void* const* d_in, const int* in_sizes, int n_in,
                              void* d_out, int out_size) {
    const float* xs      = (const float*)d_in[0];
    const int*   task_id = (const int*)d_in[1];
    const int*   action  = (const int*)d_in[2];
    const float* W       = (const float*)d_in[3];
    const float* bias    = (const float*)d_in[4];
    float*       out     = (float*)d_out;

    setup_kernel<<<TT, 256>>>(task_id);
    dim3 grid(TT, NSLOT, KSPLIT);
    logits_kernel<<<grid, 256>>>(xs, W);
    softmax_kernel<<<BB / RW, 256>>>(task_id, action, bias, out);
}